// round 15
// baseline (speedup 1.0000x reference)
#include <cuda_runtime.h>
#include <cuda_fp16.h>
#include <math.h>
#include <stdint.h>

// Seq2seq LSTM forward, sm_103a. All GEMMs 2-term fp16.
//   (1) vocab tables P = embed16 @ Wih16'(2-term)^T + b'
//   (2) persistent-grid recurrence: h fp16 via TMA bulk copies (chunk-padded
//       global layout, 8 bulk loads/step), W fp16 [hi|lo] resident in smem
//   (3) logits = Hdec16 @ outW16(2-term)^T + out_b
#define NBLK 128
#define B_   64
#define T_   256
#define V_   8000
#define E_   512
#define H_   1024
#define G4H  4096
#define TDEC 255
#define START_TOK 1

#define MPAD_LOGITS 16384
#define NPAD_LOGITS 8192
#define MPAD_TAB    8064

#define GEMM_SMEM   98304           // 2 stages x (A 16KB + Bhi 16KB + Blo 16KB)

// recurrence smem: W16 131072 | h ring 4x17408 | c 2048 | tok 256 | mbar 64
#define RSTG        17408           // one h chunk: 64 rows x 272 B
#define RW_OFF      0
#define RH_OFF      131072
#define RC_OFF      (RH_OFF + 4 * RSTG)      // 200704
#define RT_OFF      (RC_OFF + 2048)          // 202752
#define RM_OFF      (RT_OFF + 256)           // 203008
#define REC_SMEM    (RM_OFF + 64)            // 203072

#define HBUF        (8 * RSTG)               // 139264 B per h buffer

// ---------------- PTX helpers -------------------------------------------------------
__device__ __forceinline__ uint32_t smem_u32(const void* p) {
    uint32_t a;
    asm("{ .reg .u64 t; cvta.to.shared.u64 t, %1; cvt.u32.u64 %0, t; }" : "=r"(a) : "l"(p));
    return a;
}
__device__ __forceinline__ uint32_t sw128(uint32_t off) {
    return off ^ ((off >> 3) & 0x70);
}
__device__ __forceinline__ void cp_async16(uint32_t dst, const void* src) {
    asm volatile("cp.async.cg.shared.global [%0], [%1], 16;" :: "r"(dst), "l"(src) : "memory");
}
#define CP_COMMIT() asm volatile("cp.async.commit_group;" ::: "memory")
template<int N> __device__ __forceinline__ void cp_wait() {
    asm volatile("cp.async.wait_group %0;" :: "n"(N) : "memory");
}
__device__ __forceinline__ void bulk_g2s(uint32_t dst, const void* src,
                                         uint32_t bytes, uint32_t mbar) {
    asm volatile(
        "cp.async.bulk.shared::cluster.global.mbarrier::complete_tx::bytes "
        "[%0], [%1], %2, [%3];"
        :: "r"(dst), "l"(src), "r"(bytes), "r"(mbar) : "memory");
}
#define MBARRIER_INIT(mbar, cnt) \
    asm volatile("mbarrier.init.shared.b64 [%0], %1;" :: "r"(mbar), "r"((uint32_t)(cnt)) : "memory")
#define MBARRIER_EXPECT_TX(mbar, tx) \
    asm volatile("mbarrier.arrive.expect_tx.shared.b64 _, [%0], %1;" \
                 :: "r"(mbar), "r"((uint32_t)(tx)) : "memory")
#define MBARRIER_WAIT_PARITY(mbar, par) do {                                   \
    uint32_t _m = (mbar), _p = (par), _d;                                      \
    asm volatile("{\n\t.reg .pred p;\n\t"                                      \
        "mbarrier.try_wait.parity.acquire.cta.shared::cta.b64 p, [%1], %2;\n\t"\
        "selp.b32 %0, 1, 0, p;\n\t}" : "=r"(_d) : "r"(_m), "r"(_p) : "memory");\
    if (!_d) {                                                                 \
        asm volatile("{\n\t.reg .pred P1;\n\t"                                 \
            "WL_%=:\n\t"                                                       \
            "mbarrier.try_wait.parity.acquire.cta.shared::cta.b64 P1, [%0], %1, 0x989680;\n\t" \
            "@P1 bra.uni WD_%=;\n\t"                                           \
            "bra.uni WL_%=;\n\t"                                               \
            "WD_%=:\n\t}" :: "r"(_m), "r"(_p) : "memory");                     \
    }                                                                          \
} while (0)
__device__ __forceinline__ void ldsm_x4(uint32_t r[4], uint32_t addr) {
    asm volatile("ldmatrix.sync.aligned.m8n8.x4.shared.b16 {%0,%1,%2,%3}, [%4];"
                 : "=r"(r[0]), "=r"(r[1]), "=r"(r[2]), "=r"(r[3]) : "r"(addr));
}
__device__ __forceinline__ void mma_f16(float d[4], const uint32_t a[4],
                                        uint32_t b0, uint32_t b1) {
    asm volatile(
        "mma.sync.aligned.m16n8k16.row.col.f32.f16.f16.f32 "
        "{%0,%1,%2,%3}, {%4,%5,%6,%7}, {%8,%9}, {%0,%1,%2,%3};"
        : "+f"(d[0]), "+f"(d[1]), "+f"(d[2]), "+f"(d[3])
        : "r"(a[0]), "r"(a[1]), "r"(a[2]), "r"(a[3]), "r"(b0), "r"(b1));
}

// ---------------- device scratch (allocation-free rule) -----------------------------
__device__ float g_P_enc[(size_t)V_ * G4H];
__device__ float g_P_dec[(size_t)V_ * G4H];
__device__ __half g_A16[(size_t)MPAD_LOGITS * H_];      // GEMM A operand (reused)
__device__ __half g_B16[(size_t)NPAD_LOGITS * 2 * H_];  // GEMM B operand [hi|lo]
__device__ __half g_W16_e[(size_t)G4H * 2048];          // recurrence W, reordered [hi|lo]
__device__ __half g_W16_d[(size_t)G4H * 2048];
// h buffers, chunk-padded: [2][8 chunks][64 rows][272 B] (cols 0..255 data, 256..271 pad)
__device__ __align__(256) unsigned char g_h16raw[2 * HBUF];
__device__ float g_bias_r[G4H];
__device__ unsigned g_arrive = 0;
__device__ unsigned g_phase  = 0;

// ---------------- conversion helpers ------------------------------------------------
template<int REORD>
__global__ void to_f16(const float* __restrict__ X, __half* __restrict__ Y,
                       int M_in, int M_pad, int K)
{
    int idx = blockIdx.x * blockDim.x + threadIdx.x;
    if (idx >= M_pad * K) return;
    int m = idx / K, k = idx - m * K;
    int src = m;
    if (REORD) {
        int blk = m >> 5, r = m & 31;
        src = (r >> 3) * H_ + blk * 8 + (r & 7);
    }
    float x = (src < M_in) ? X[(size_t)src * K + k] : 0.f;
    Y[(size_t)m * K + k] = __float2half_rn(x);
}

template<int REORD>
__global__ void split2_f16(const float* __restrict__ X, __half* __restrict__ Y,
                           int M_in, int M_pad, int K)
{
    int idx = blockIdx.x * blockDim.x + threadIdx.x;
    if (idx >= M_pad * K) return;
    int m = idx / K, k = idx - m * K;
    int src = m;
    if (REORD) {
        int blk = m >> 5, r = m & 31;
        src = (r >> 3) * H_ + blk * 8 + (r & 7);
    }
    float x = (src < M_in) ? X[(size_t)src * K + k] : 0.f;
    __half hi = __float2half_rn(x);
    __half lo = __float2half_rn(x - __half2float(hi));
    size_t rb = (size_t)m * (2 * K);
    Y[rb + k]     = hi;
    Y[rb + K + k] = lo;
}

__global__ void reorder_bias(const float* __restrict__ b, float* __restrict__ br) {
    int m = blockIdx.x * blockDim.x + threadIdx.x;
    if (m >= G4H) return;
    int blk = m >> 5, r = m & 31;
    br[m] = b[(r >> 3) * H_ + blk * 8 + (r & 7)];
}

__global__ void zero_buf(float4* p, size_t n16) {
    size_t i = (size_t)blockIdx.x * blockDim.x + threadIdx.x;
    if (i < n16) p[i] = make_float4(0.f, 0.f, 0.f, 0.f);
}

// ---------------- 2-term fp16 HMMA GEMM ---------------------------------------------
// C[M,N] = A16[M,K] @ (B16hi + B16lo)[N,K]^T + bias;  B16 stored [N, 2K] = [hi|lo].
// 128x128 tiles, 64-col chunks (128B sw128 rows), 2-stage ring, 2 CTAs/SM.
// MODE 0: row-major C.  MODE 1: logits remap m=t*64+b -> C[(b*255+t)*ldC + n]
template<int MODE>
__global__ void __launch_bounds__(256, 2) mma_nt2(
    const __half* __restrict__ A16, const __half* __restrict__ B16,
    const float* __restrict__ bias, float* __restrict__ C,
    int M_eff, int N_eff, int K, int ldC)
{
    extern __shared__ __align__(1024) char dsm[];
    const uint32_t sb = smem_u32(dsm);
    const int tid = threadIdx.x;
    const int wid = tid >> 5, lid = tid & 31;
    const int wm = wid & 3, wn = wid >> 2;
    const int bm = blockIdx.y * 128, bn = blockIdx.x * 128;
    const int nch = K / 64;

    auto loadT = [&](int ch) {
        uint32_t stg = sb + (ch & 1) * 49152;
#pragma unroll
        for (int j = 0; j < 4; j++) {
            int i = tid + j * 256;
            int r = i >> 3, cb = (i & 7) * 16;
            uint32_t off = sw128((uint32_t)(r * 128 + cb));
            cp_async16(stg + off,
                       (const char*)A16 + ((size_t)(bm + r) * K + ch * 64) * 2 + cb);
            cp_async16(stg + 16384 + off,
                       (const char*)B16 + ((size_t)(bn + r) * 2 * K + ch * 64) * 2 + cb);
            cp_async16(stg + 32768 + off,
                       (const char*)B16 + ((size_t)(bn + r) * 2 * K + K + ch * 64) * 2 + cb);
        }
        CP_COMMIT();
    };

    float acc[2][8][4];
#pragma unroll
    for (int i = 0; i < 2; i++)
#pragma unroll
        for (int j = 0; j < 8; j++)
#pragma unroll
            for (int q = 0; q < 4; q++) acc[i][j][q] = 0.f;

    loadT(0);
    for (int i = 0; i < nch; i++) {
        if (i + 1 < nch) { loadT(i + 1); cp_wait<1>(); }
        else             { cp_wait<0>(); }
        __syncthreads();
        const uint32_t ab  = sb + (i & 1) * 49152;
        const uint32_t bhb = ab + 16384;
        const uint32_t blb = ab + 32768;
#pragma unroll
        for (int ks = 0; ks < 4; ks++) {
            const uint32_t kb = (uint32_t)((ks * 16 + ((lid >> 4) << 3)) * 2);
            uint32_t a[2][4], b[4][4];
#pragma unroll
            for (int mi = 0; mi < 2; mi++)
                ldsm_x4(a[mi], ab + sw128((uint32_t)((wm * 32 + mi * 16 + (lid & 15)) * 128) + kb));
#pragma unroll
            for (int ni = 0; ni < 4; ni++)
                ldsm_x4(b[ni], bhb + sw128((uint32_t)((wn * 64 + ni * 16 + (lid & 15)) * 128) + kb));
#pragma unroll
            for (int mi = 0; mi < 2; mi++)
#pragma unroll
                for (int ni = 0; ni < 4; ni++) {
                    mma_f16(acc[mi][2 * ni + 0], a[mi], b[ni][0], b[ni][2]);
                    mma_f16(acc[mi][2 * ni + 1], a[mi], b[ni][1], b[ni][3]);
                }
#pragma unroll
            for (int ni = 0; ni < 4; ni++)
                ldsm_x4(b[ni], blb + sw128((uint32_t)((wn * 64 + ni * 16 + (lid & 15)) * 128) + kb));
#pragma unroll
            for (int mi = 0; mi < 2; mi++)
#pragma unroll
                for (int ni = 0; ni < 4; ni++) {
                    mma_f16(acc[mi][2 * ni + 0], a[mi], b[ni][0], b[ni][2]);
                    mma_f16(acc[mi][2 * ni + 1], a[mi], b[ni][1], b[ni][3]);
                }
        }
        __syncthreads();
    }

#pragma unroll
    for (int mi = 0; mi < 2; mi++) {
        int m0 = bm + wm * 32 + mi * 16 + (lid >> 2);
#pragma unroll
        for (int half = 0; half < 2; half++) {
            int m = m0 + half * 8;
            if (m >= M_eff) continue;
            size_t obase;
            if (MODE == 0) obase = (size_t)m * ldC;
            else {
                int t = m >> 6, b = m & 63;
                obase = ((size_t)b * TDEC + t) * ldC;
            }
#pragma unroll
            for (int nj = 0; nj < 8; nj++) {
                int n = bn + wn * 64 + nj * 8 + (lid & 3) * 2;
                float v0 = acc[mi][nj][half * 2 + 0];
                float v1 = acc[mi][nj][half * 2 + 1];
                if (n < N_eff)     C[obase + n]     = v0 + __ldg(&bias[n]);
                if (n + 1 < N_eff) C[obase + n + 1] = v1 + __ldg(&bias[n + 1]);
            }
        }
    }
}

// ---------------- persistent HMMA LSTM recurrence (fp16 h via TMA bulk) -------------
// 128 blocks x 256 thr; block owns 32 reordered gate rows (4 gates x 8 hidden units).
// W16' = [hi|lo] (32 x 2048 fp16, sw128) resident in smem across all 511 steps.
// h global layout: 8 chunks x (64 rows x 272B padded). Per step: 8 bulk TMA loads
// (one 17408B copy each) into a 4-stage ring; per chunk 2 MMA terms (fp32 accum).
__global__ void __launch_bounds__(256, 1) lstm_rec_mma(
    const int* __restrict__ seqs,
    const __half* __restrict__ W16_e,
    const __half* __restrict__ W16_d,
    __half* __restrict__ Hdec16)
{
    extern __shared__ __align__(1024) char dsm[];
    const uint32_t sb = smem_u32(dsm);
    float* gate_s = (float*)(dsm + RH_OFF);      // [64][33], aliases ring stage 0
    float* c_s    = (float*)(dsm + RC_OFF);      // [512]: p = jj*64 + b
    int*   tok_s  = (int*)  (dsm + RT_OFF);

    const int tid = threadIdx.x;
    const int bid = blockIdx.x;
    const int wid = tid >> 5, lid = tid & 31;
    const int wm = wid & 3, wn = wid >> 2;

    unsigned base = 0;
    if (tid == 0) base = atomicAdd(&g_phase, 0u);   // replay-safe phase baseline
    unsigned tgt = 0;

    // zero h buffer 0 (padded) and cell state; init 8 chunk mbarriers
    for (int i = bid * 256 + tid; i < HBUF / 4; i += NBLK * 256)
        ((uint32_t*)g_h16raw)[i] = 0u;
    c_s[tid] = 0.f; c_s[tid + 256] = 0.f;
    if (tid == 0) {
#pragma unroll
        for (int m = 0; m < 8; m++) MBARRIER_INIT(sb + RM_OFF + m * 8, 1);
    }

    auto loadW = [&](const __half* Wsrc) {
#pragma unroll
        for (int j = 0; j < 32; j++) {
            int i = tid + j * 256;
            int row = i >> 8;
            int cb  = (i & 255) * 16;
            int ci  = cb >> 7, inner = cb & 127;
            cp_async16(sb + RW_OFF + ci * 4096 + sw128((uint32_t)(row * 128 + inner)),
                       (const char*)Wsrc + (size_t)(bid * 32 + row) * 4096 + cb);
        }
        CP_COMMIT();
    };
    loadW(W16_e);

#define GSYNC() do {                                                     \
    __syncthreads();                                                     \
    if (tid == 0) {                                                      \
        ++tgt;                                                           \
        __threadfence();                                                 \
        unsigned prev_ = atomicAdd(&g_arrive, 1u);                       \
        if (prev_ == NBLK - 1) {                                         \
            atomicExch(&g_arrive, 0u);                                   \
            __threadfence();                                             \
            atomicAdd(&g_phase, 1u);                                     \
        } else {                                                         \
            volatile unsigned* vp_ = &g_phase;                           \
            while ((unsigned)(*vp_ - base) < tgt)                        \
                __nanosleep(32);                                         \
            __threadfence();                                             \
        }                                                                \
    }                                                                    \
    __syncthreads();                                                     \
} while (0)

    GSYNC();              // h0 + mbarrier init visible
    cp_wait<0>();         // encoder W resident
    __syncthreads();

    for (int s = 0; s < T_ + TDEC; s++) {
        const bool enc = (s < T_);
        const int t = enc ? s : s - T_;
        const float* __restrict__ P = enc ? g_P_enc : g_P_dec;
        const unsigned char* hsrc = g_h16raw + (size_t)(s & 1) * HBUF;

        if (s == T_) {                      // decoder weight swap (one-time stall)
            loadW(W16_d);
            cp_wait<0>();
            __syncthreads();
        }
        if (tid < B_)
            tok_s[tid] = enc ? seqs[tid * T_ + t]
                             : (t == 0 ? START_TOK : seqs[tid * T_ + t]);

        // one bulk TMA copy per chunk, issued by thread 0
        auto issueH = [&](int ch) {
            if (tid == 0) {
                uint32_t mb = sb + RM_OFF + ch * 8;
                MBARRIER_EXPECT_TX(mb, RSTG);
                bulk_g2s(sb + RH_OFF + (ch & 3) * RSTG,
                         hsrc + (size_t)ch * RSTG, RSTG, mb);
            }
        };

        float accL[4] = {0.f, 0.f, 0.f, 0.f};
        float accH[4] = {0.f, 0.f, 0.f, 0.f};
        issueH(0); issueH(1); issueH(2);

        for (int ch = 0; ch < 8; ch++) {
            MBARRIER_WAIT_PARITY(sb + RM_OFF + ch * 8, (uint32_t)(s & 1));
            __syncthreads();                 // all warps done with stage (ch-1)
            if (ch + 3 < 8) issueH(ch + 3);  // targets stage (ch-1)&3, now free
            const uint32_t hstage = sb + RH_OFF + (ch & 3) * RSTG;
#pragma unroll
            for (int half = 0; half < 2; half++) {
                const uint32_t wbh = sb + RW_OFF + (2 * ch + half) * 4096;
                const uint32_t wbl = sb + RW_OFF + (16 + 2 * ch + half) * 4096;
#pragma unroll
                for (int ks = 0; ks < 4; ks++) {
                    const uint32_t kb = (uint32_t)((ks * 16 + ((lid >> 4) << 3)) * 2);
                    const uint32_t arow = (uint32_t)((wm * 16 + (lid & 15)) * 272
                                                     + half * 128) + kb;
                    const uint32_t brow = sw128((uint32_t)((wn * 16 + (lid & 15)) * 128) + kb);
                    uint32_t a[4], bh[4], bl[4];
                    ldsm_x4(a,  hstage + arow);
                    ldsm_x4(bh, wbh + brow);
                    ldsm_x4(bl, wbl + brow);
                    mma_f16(accL, a, bh[0], bh[2]); mma_f16(accH, a, bh[1], bh[3]);
                    mma_f16(accL, a, bl[0], bl[2]); mma_f16(accH, a, bl[1], bl[3]);
                }
            }
        }
        __syncthreads();                     // ring reads done -> gate_s alias safe

        {
            int r0 = wm * 16 + (lid >> 2);
            int c0 = wn * 16 + (lid & 3) * 2;
            gate_s[r0 * 33 + c0]           = accL[0];
            gate_s[r0 * 33 + c0 + 1]       = accL[1];
            gate_s[(r0 + 8) * 33 + c0]     = accL[2];
            gate_s[(r0 + 8) * 33 + c0 + 1] = accL[3];
            gate_s[r0 * 33 + c0 + 8]       = accH[0];
            gate_s[r0 * 33 + c0 + 9]       = accH[1];
            gate_s[(r0 + 8) * 33 + c0 + 8] = accH[2];
            gate_s[(r0 + 8) * 33 + c0 + 9] = accH[3];
        }
        __syncthreads();

#pragma unroll
        for (int u = 0; u < 2; u++) {
            int p = tid + u * 256;
            int b = p & 63, jj = p >> 6;
            const float* Prow = P + (size_t)tok_s[b] * G4H + bid * 32;
            float gi = gate_s[b * 33 + jj]      + __ldg(&Prow[jj]);
            float gf = gate_s[b * 33 + 8 + jj]  + __ldg(&Prow[8 + jj]);
            float gg = gate_s[b * 33 + 16 + jj] + __ldg(&Prow[16 + jj]);
            float go = gate_s[b * 33 + 24 + jj] + __ldg(&Prow[24 + jj]);
            float c = c_s[p];
            float si = 1.f / (1.f + expf(-gi));
            float sf = 1.f / (1.f + expf(-gf));
            float so = 1.f / (1.f + expf(-go));
            float cn = sf * c + si * tanhf(gg);
            float hn = so * tanhf(cn);
            c_s[p] = cn;
            int jg = bid * 8 + jj;
            __half hv = __float2half_rn(hn);
            int chk = jg >> 7, col = jg & 127;
            *(__half*)(g_h16raw + (size_t)((s + 1) & 1) * HBUF
                       + (size_t)chk * RSTG + b * 272 + col * 2) = hv;
            if (!enc)
                Hdec16[(size_t)(t * 64 + b) * H_ + jg] = hv;
        }
        GSYNC();
    }
#undef GSYNC
}

// ---------------- launch ------------------------------------------------------------
extern "C" void kernel_launch(void* const* d_in, const int* in_sizes, int n_in,
                              void* d_out, int out_size)
{
    (void)in_sizes; (void)n_in; (void)out_size;
    const int*   seqs    = (const int*)  d_in[1];
    const float* enc_emb = (const float*)d_in[2];
    const float* enc_Wih = (const float*)d_in[3];
    const float* enc_Whh = (const float*)d_in[4];
    const float* enc_b   = (const float*)d_in[5];
    const float* dec_emb = (const float*)d_in[6];
    const float* dec_Wih = (const float*)d_in[7];
    const float* dec_Whh = (const float*)d_in[8];
    const float* dec_b   = (const float*)d_in[9];
    const float* out_W   = (const float*)d_in[10];
    const float* out_b   = (const float*)d_in[11];
    float* out = (float*)d_out;

    float *Penc, *Pdec, *biasr;
    __half *A16, *B16, *W16e, *W16d;
    cudaGetSymbolAddress((void**)&Penc, g_P_enc);
    cudaGetSymbolAddress((void**)&Pdec, g_P_dec);
    cudaGetSymbolAddress((void**)&A16,  g_A16);
    cudaGetSymbolAddress((void**)&B16,  g_B16);
    cudaGetSymbolAddress((void**)&W16e, g_W16_e);
    cudaGetSymbolAddress((void**)&W16d, g_W16_d);
    cudaGetSymbolAddress((void**)&biasr, g_bias_r);

    cudaFuncSetAttribute(mma_nt2<0>, cudaFuncAttributeMaxDynamicSharedMemorySize, GEMM_SMEM);
    cudaFuncSetAttribute(mma_nt2<1>, cudaFuncAttributeMaxDynamicSharedMemorySize, GEMM_SMEM);
    cudaFuncSetAttribute(lstm_rec_mma, cudaFuncAttributeMaxDynamicSharedMemorySize, REC_SMEM);

    // encoder vocab table: P_enc = enc_emb16 @ enc_Wih'(2-term)^T + b'  [8000,4096]
    to_f16<0><<<(MPAD_TAB * E_ + 255) / 256, 256>>>(enc_emb, A16, V_, MPAD_TAB, E_);
    split2_f16<1><<<(G4H * E_ + 255) / 256, 256>>>(enc_Wih, B16, G4H, G4H, E_);
    reorder_bias<<<16, 256>>>(enc_b, biasr);
    mma_nt2<0><<<dim3(G4H / 128, MPAD_TAB / 128), 256, GEMM_SMEM>>>(
        A16, B16, biasr, Penc, V_, G4H, E_, G4H);

    // decoder vocab table
    to_f16<0><<<(MPAD_TAB * E_ + 255) / 256, 256>>>(dec_emb, A16, V_, MPAD_TAB, E_);
    split2_f16<1><<<(G4H * E_ + 255) / 256, 256>>>(dec_Wih, B16, G4H, G4H, E_);
    reorder_bias<<<16, 256>>>(dec_b, biasr);
    mma_nt2<0><<<dim3(G4H / 128, MPAD_TAB / 128), 256, GEMM_SMEM>>>(
        A16, B16, biasr, Pdec, V_, G4H, E_, G4H);

    // recurrence weights (reordered, fp16 [hi|lo]); logits B operand; zero A16 pad tail
    split2_f16<1><<<(G4H * H_ + 255) / 256, 256>>>(enc_Whh, W16e, G4H, G4H, H_);
    split2_f16<1><<<(G4H * H_ + 255) / 256, 256>>>(dec_Whh, W16d, G4H, G4H, H_);
    split2_f16<0><<<(NPAD_LOGITS * H_ + 255) / 256, 256>>>(out_W, B16, V_, NPAD_LOGITS, H_);
    zero_buf<<<32, 256>>>((float4*)(A16 + (size_t)(TDEC * B_) * H_),
                          ((size_t)(MPAD_LOGITS - TDEC * B_) * H_ * 2) / 16);

    // serial recurrence (persistent grid; decoder h written directly into A16)
    lstm_rec_mma<<<NBLK, 256, REC_SMEM>>>(seqs, W16e, W16d, A16);

    // logits = Hdec16 @ outW16(2-term)^T + out_b -> [B, 255, V]
    mma_nt2<1><<<dim3(NPAD_LOGITS / 128, MPAD_LOGITS / 128), 256, GEMM_SMEM>>>(
        A16, B16, out_b, out, TDEC * B_, V_, H_, V_);
}

// round 16
// speedup vs baseline: 1.1291x; 1.1291x over previous
#include <cuda_runtime.h>
#include <cuda_fp16.h>
#include <math.h>
#include <stdint.h>

// Seq2seq LSTM forward, sm_103a. All GEMMs 2-term fp16.
//   (1) vocab tables P = embed16 @ Wih16'(2-term)^T + b'
//   (2) persistent-grid recurrence: h stored in GLOBAL pre-swizzled into
//       mma.sync A-fragment order -> one LDG.128 per fragment per lane,
//       no h smem ring, no per-chunk barriers. W fp16 [hi|lo] smem-resident.
//   (3) logits = Hdec16 @ outW16(2-term)^T + out_b
#define NBLK 128
#define B_   64
#define T_   256
#define V_   8000
#define E_   512
#define H_   1024
#define G4H  4096
#define TDEC 255
#define START_TOK 1

#define MPAD_LOGITS 16384
#define NPAD_LOGITS 8192
#define MPAD_TAB    8064

#define GEMM_SMEM   98304           // 2 stages x (A 16KB + Bhi 16KB + Blo 16KB)

// recurrence smem: W16 131072 | gate_s 8448 | c 2048 | tok 256
#define RW_OFF      0
#define RG_OFF      131072
#define RC_OFF      139520
#define RT_OFF      141568
#define REC_SMEM    141824

#define HFRAG_BYTES 131072          // one h buffer in fragment order (64x1024 fp16)

// ---------------- PTX helpers -------------------------------------------------------
__device__ __forceinline__ uint32_t smem_u32(const void* p) {
    uint32_t a;
    asm("{ .reg .u64 t; cvta.to.shared.u64 t, %1; cvt.u32.u64 %0, t; }" : "=r"(a) : "l"(p));
    return a;
}
__device__ __forceinline__ uint32_t sw128(uint32_t off) {
    return off ^ ((off >> 3) & 0x70);
}
__device__ __forceinline__ void cp_async16(uint32_t dst, const void* src) {
    asm volatile("cp.async.cg.shared.global [%0], [%1], 16;" :: "r"(dst), "l"(src) : "memory");
}
#define CP_COMMIT() asm volatile("cp.async.commit_group;" ::: "memory")
template<int N> __device__ __forceinline__ void cp_wait() {
    asm volatile("cp.async.wait_group %0;" :: "n"(N) : "memory");
}
__device__ __forceinline__ void ldsm_x4(uint32_t r[4], uint32_t addr) {
    asm volatile("ldmatrix.sync.aligned.m8n8.x4.shared.b16 {%0,%1,%2,%3}, [%4];"
                 : "=r"(r[0]), "=r"(r[1]), "=r"(r[2]), "=r"(r[3]) : "r"(addr));
}
__device__ __forceinline__ void ldg4(uint32_t r[4], const void* p) {
    asm volatile("ld.global.nc.v4.u32 {%0,%1,%2,%3}, [%4];"
                 : "=r"(r[0]), "=r"(r[1]), "=r"(r[2]), "=r"(r[3]) : "l"(p));
}
__device__ __forceinline__ void mma_f16(float d[4], const uint32_t a[4],
                                        uint32_t b0, uint32_t b1) {
    asm volatile(
        "mma.sync.aligned.m16n8k16.row.col.f32.f16.f16.f32 "
        "{%0,%1,%2,%3}, {%4,%5,%6,%7}, {%8,%9}, {%0,%1,%2,%3};"
        : "+f"(d[0]), "+f"(d[1]), "+f"(d[2]), "+f"(d[3])
        : "r"(a[0]), "r"(a[1]), "r"(a[2]), "r"(a[3]), "r"(b0), "r"(b1));
}

// ---------------- device scratch (allocation-free rule) -----------------------------
__device__ float g_P_enc[(size_t)V_ * G4H];
__device__ float g_P_dec[(size_t)V_ * G4H];
__device__ __half g_A16[(size_t)MPAD_LOGITS * H_];      // GEMM A operand (reused)
__device__ __half g_B16[(size_t)NPAD_LOGITS * 2 * H_];  // GEMM B operand [hi|lo]
__device__ __half g_W16_e[(size_t)G4H * 2048];          // recurrence W, reordered [hi|lo]
__device__ __half g_W16_d[(size_t)G4H * 2048];
// h double buffer in mma A-fragment order:
//   frag f = wm*64 + (j>>4), lane l holds 16B = {h[r][k],h[r+8][k],h[r][k+8],h[r+8][k+8]}
//   r = wm*16 + (l>>2), k = (j&~15) + (l&3)*2
__device__ __align__(256) unsigned char g_hfrag[2][HFRAG_BYTES];
__device__ float g_bias_r[G4H];
__device__ unsigned g_arrive = 0;
__device__ unsigned g_phase  = 0;

// ---------------- conversion helpers ------------------------------------------------
template<int REORD>
__global__ void to_f16(const float* __restrict__ X, __half* __restrict__ Y,
                       int M_in, int M_pad, int K)
{
    int idx = blockIdx.x * blockDim.x + threadIdx.x;
    if (idx >= M_pad * K) return;
    int m = idx / K, k = idx - m * K;
    int src = m;
    if (REORD) {
        int blk = m >> 5, r = m & 31;
        src = (r >> 3) * H_ + blk * 8 + (r & 7);
    }
    float x = (src < M_in) ? X[(size_t)src * K + k] : 0.f;
    Y[(size_t)m * K + k] = __float2half_rn(x);
}

template<int REORD>
__global__ void split2_f16(const float* __restrict__ X, __half* __restrict__ Y,
                           int M_in, int M_pad, int K)
{
    int idx = blockIdx.x * blockDim.x + threadIdx.x;
    if (idx >= M_pad * K) return;
    int m = idx / K, k = idx - m * K;
    int src = m;
    if (REORD) {
        int blk = m >> 5, r = m & 31;
        src = (r >> 3) * H_ + blk * 8 + (r & 7);
    }
    float x = (src < M_in) ? X[(size_t)src * K + k] : 0.f;
    __half hi = __float2half_rn(x);
    __half lo = __float2half_rn(x - __half2float(hi));
    size_t rb = (size_t)m * (2 * K);
    Y[rb + k]     = hi;
    Y[rb + K + k] = lo;
}

__global__ void reorder_bias(const float* __restrict__ b, float* __restrict__ br) {
    int m = blockIdx.x * blockDim.x + threadIdx.x;
    if (m >= G4H) return;
    int blk = m >> 5, r = m & 31;
    br[m] = b[(r >> 3) * H_ + blk * 8 + (r & 7)];
}

__global__ void zero_buf(float4* p, size_t n16) {
    size_t i = (size_t)blockIdx.x * blockDim.x + threadIdx.x;
    if (i < n16) p[i] = make_float4(0.f, 0.f, 0.f, 0.f);
}

// ---------------- 2-term fp16 HMMA GEMM (unchanged from 6530us kernel) --------------
// C[M,N] = A16[M,K] @ (B16hi + B16lo)[N,K]^T + bias;  B16 stored [N, 2K] = [hi|lo].
template<int MODE>
__global__ void __launch_bounds__(256, 2) mma_nt2(
    const __half* __restrict__ A16, const __half* __restrict__ B16,
    const float* __restrict__ bias, float* __restrict__ C,
    int M_eff, int N_eff, int K, int ldC)
{
    extern __shared__ __align__(1024) char dsm[];
    const uint32_t sb = smem_u32(dsm);
    const int tid = threadIdx.x;
    const int wid = tid >> 5, lid = tid & 31;
    const int wm = wid & 3, wn = wid >> 2;
    const int bm = blockIdx.y * 128, bn = blockIdx.x * 128;
    const int nch = K / 64;

    auto loadT = [&](int ch) {
        uint32_t stg = sb + (ch & 1) * 49152;
#pragma unroll
        for (int j = 0; j < 4; j++) {
            int i = tid + j * 256;
            int r = i >> 3, cb = (i & 7) * 16;
            uint32_t off = sw128((uint32_t)(r * 128 + cb));
            cp_async16(stg + off,
                       (const char*)A16 + ((size_t)(bm + r) * K + ch * 64) * 2 + cb);
            cp_async16(stg + 16384 + off,
                       (const char*)B16 + ((size_t)(bn + r) * 2 * K + ch * 64) * 2 + cb);
            cp_async16(stg + 32768 + off,
                       (const char*)B16 + ((size_t)(bn + r) * 2 * K + K + ch * 64) * 2 + cb);
        }
        CP_COMMIT();
    };

    float acc[2][8][4];
#pragma unroll
    for (int i = 0; i < 2; i++)
#pragma unroll
        for (int j = 0; j < 8; j++)
#pragma unroll
            for (int q = 0; q < 4; q++) acc[i][j][q] = 0.f;

    loadT(0);
    for (int i = 0; i < nch; i++) {
        if (i + 1 < nch) { loadT(i + 1); cp_wait<1>(); }
        else             { cp_wait<0>(); }
        __syncthreads();
        const uint32_t ab  = sb + (i & 1) * 49152;
        const uint32_t bhb = ab + 16384;
        const uint32_t blb = ab + 32768;
#pragma unroll
        for (int ks = 0; ks < 4; ks++) {
            const uint32_t kb = (uint32_t)((ks * 16 + ((lid >> 4) << 3)) * 2);
            uint32_t a[2][4], b[4][4];
#pragma unroll
            for (int mi = 0; mi < 2; mi++)
                ldsm_x4(a[mi], ab + sw128((uint32_t)((wm * 32 + mi * 16 + (lid & 15)) * 128) + kb));
#pragma unroll
            for (int ni = 0; ni < 4; ni++)
                ldsm_x4(b[ni], bhb + sw128((uint32_t)((wn * 64 + ni * 16 + (lid & 15)) * 128) + kb));
#pragma unroll
            for (int mi = 0; mi < 2; mi++)
#pragma unroll
                for (int ni = 0; ni < 4; ni++) {
                    mma_f16(acc[mi][2 * ni + 0], a[mi], b[ni][0], b[ni][2]);
                    mma_f16(acc[mi][2 * ni + 1], a[mi], b[ni][1], b[ni][3]);
                }
#pragma unroll
            for (int ni = 0; ni < 4; ni++)
                ldsm_x4(b[ni], blb + sw128((uint32_t)((wn * 64 + ni * 16 + (lid & 15)) * 128) + kb));
#pragma unroll
            for (int mi = 0; mi < 2; mi++)
#pragma unroll
                for (int ni = 0; ni < 4; ni++) {
                    mma_f16(acc[mi][2 * ni + 0], a[mi], b[ni][0], b[ni][2]);
                    mma_f16(acc[mi][2 * ni + 1], a[mi], b[ni][1], b[ni][3]);
                }
        }
        __syncthreads();
    }

#pragma unroll
    for (int mi = 0; mi < 2; mi++) {
        int m0 = bm + wm * 32 + mi * 16 + (lid >> 2);
#pragma unroll
        for (int half = 0; half < 2; half++) {
            int m = m0 + half * 8;
            if (m >= M_eff) continue;
            size_t obase;
            if (MODE == 0) obase = (size_t)m * ldC;
            else {
                int t = m >> 6, b = m & 63;
                obase = ((size_t)b * TDEC + t) * ldC;
            }
#pragma unroll
            for (int nj = 0; nj < 8; nj++) {
                int n = bn + wn * 64 + nj * 8 + (lid & 3) * 2;
                float v0 = acc[mi][nj][half * 2 + 0];
                float v1 = acc[mi][nj][half * 2 + 1];
                if (n < N_eff)     C[obase + n]     = v0 + __ldg(&bias[n]);
                if (n + 1 < N_eff) C[obase + n + 1] = v1 + __ldg(&bias[n + 1]);
            }
        }
    }
}

// ---------------- persistent HMMA LSTM recurrence (register-direct A) ---------------
// 128 blocks x 256 thr; block owns 32 reordered gate rows (4 gates x 8 hidden units).
// W16' = [hi|lo] (32 x 2048 fp16, sw128) resident in smem across all 511 steps.
// h read straight from fragment-ordered global: 16 kk-iters x 4 ks, one LDG.128
// per fragment per lane; per ks 4 MMAs (hi+lo terms, fp32 accum). No h smem.
__global__ void __launch_bounds__(256, 1) lstm_rec_mma(
    const int* __restrict__ seqs,
    const __half* __restrict__ W16_e,
    const __half* __restrict__ W16_d,
    __half* __restrict__ Hdec16)
{
    extern __shared__ __align__(1024) char dsm[];
    const uint32_t sb = smem_u32(dsm);
    float* gate_s = (float*)(dsm + RG_OFF);      // [64][33]
    float* c_s    = (float*)(dsm + RC_OFF);      // [512]: p = jj*64 + b
    int*   tok_s  = (int*)  (dsm + RT_OFF);

    const int tid = threadIdx.x;
    const int bid = blockIdx.x;
    const int wid = tid >> 5, lid = tid & 31;
    const int wm = wid & 3, wn = wid >> 2;

    unsigned base = 0;
    if (tid == 0) base = atomicAdd(&g_phase, 0u);   // replay-safe phase baseline
    unsigned tgt = 0;

    // zero h fragment buffer 0 and cell state
    for (int i = bid * 256 + tid; i < HFRAG_BYTES / 4; i += NBLK * 256)
        ((uint32_t*)g_hfrag[0])[i] = 0u;
    c_s[tid] = 0.f; c_s[tid + 256] = 0.f;

    auto loadW = [&](const __half* Wsrc) {
#pragma unroll
        for (int j = 0; j < 32; j++) {
            int i = tid + j * 256;
            int row = i >> 8;
            int cb  = (i & 255) * 16;
            int ci  = cb >> 7, inner = cb & 127;
            cp_async16(sb + RW_OFF + ci * 4096 + sw128((uint32_t)(row * 128 + inner)),
                       (const char*)Wsrc + (size_t)(bid * 32 + row) * 4096 + cb);
        }
        CP_COMMIT();
    };
    loadW(W16_e);

#define GSYNC() do {                                                     \
    __syncthreads();                                                     \
    if (tid == 0) {                                                      \
        ++tgt;                                                           \
        __threadfence();                                                 \
        unsigned prev_ = atomicAdd(&g_arrive, 1u);                       \
        if (prev_ == NBLK - 1) {                                         \
            atomicExch(&g_arrive, 0u);                                   \
            __threadfence();                                             \
            atomicAdd(&g_phase, 1u);                                     \
        } else {                                                         \
            volatile unsigned* vp_ = &g_phase;                           \
            while ((unsigned)(*vp_ - base) < tgt)                        \
                __nanosleep(32);                                         \
            __threadfence();                                             \
        }                                                                \
    }                                                                    \
    __syncthreads();                                                     \
} while (0)

    GSYNC();              // h0 visible grid-wide
    cp_wait<0>();         // encoder W resident
    __syncthreads();

    for (int s = 0; s < T_ + TDEC; s++) {
        const bool enc = (s < T_);
        const int t = enc ? s : s - T_;
        const float* __restrict__ P = enc ? g_P_enc : g_P_dec;
        // this warp's fragment stream: wm block of 64 frags x 512B, lane offset
        const char* abase = (const char*)g_hfrag[s & 1]
                          + (size_t)wm * 32768 + (size_t)lid * 16;

        if (s == T_) {                      // decoder weight swap (one-time stall)
            loadW(W16_d);
            cp_wait<0>();
            __syncthreads();
        }
        if (tid < B_)
            tok_s[tid] = enc ? seqs[tid * T_ + t]
                             : (t == 0 ? START_TOK : seqs[tid * T_ + t]);

        float accL[4] = {0.f, 0.f, 0.f, 0.f};
        float accH[4] = {0.f, 0.f, 0.f, 0.f};

        uint32_t Abuf[2][4][4];
#pragma unroll
        for (int ks = 0; ks < 4; ks++)
            ldg4(Abuf[0][ks], abase + ks * 512);

#pragma unroll
        for (int kk = 0; kk < 16; kk++) {
            if (kk < 15) {
#pragma unroll
                for (int ks = 0; ks < 4; ks++)
                    ldg4(Abuf[(kk + 1) & 1][ks], abase + ((kk + 1) * 4 + ks) * 512);
            }
            const uint32_t wbh = sb + RW_OFF + kk * 4096;
            const uint32_t wbl = sb + RW_OFF + (16 + kk) * 4096;
#pragma unroll
            for (int ks = 0; ks < 4; ks++) {
                const uint32_t kb = (uint32_t)((ks * 16 + ((lid >> 4) << 3)) * 2);
                const uint32_t brow = sw128((uint32_t)((wn * 16 + (lid & 15)) * 128) + kb);
                uint32_t bh[4], bl[4];
                ldsm_x4(bh, wbh + brow);
                ldsm_x4(bl, wbl + brow);
                mma_f16(accL, Abuf[kk & 1][ks], bh[0], bh[2]);
                mma_f16(accH, Abuf[kk & 1][ks], bh[1], bh[3]);
                mma_f16(accL, Abuf[kk & 1][ks], bl[0], bl[2]);
                mma_f16(accH, Abuf[kk & 1][ks], bl[1], bl[3]);
            }
        }

        {
            int r0 = wm * 16 + (lid >> 2);
            int c0 = wn * 16 + (lid & 3) * 2;
            gate_s[r0 * 33 + c0]           = accL[0];
            gate_s[r0 * 33 + c0 + 1]       = accL[1];
            gate_s[(r0 + 8) * 33 + c0]     = accL[2];
            gate_s[(r0 + 8) * 33 + c0 + 1] = accL[3];
            gate_s[r0 * 33 + c0 + 8]       = accH[0];
            gate_s[r0 * 33 + c0 + 9]       = accH[1];
            gate_s[(r0 + 8) * 33 + c0 + 8] = accH[2];
            gate_s[(r0 + 8) * 33 + c0 + 9] = accH[3];
        }
        __syncthreads();

#pragma unroll
        for (int u = 0; u < 2; u++) {
            int p = tid + u * 256;
            int b = p & 63, jj = p >> 6;
            const float* Prow = P + (size_t)tok_s[b] * G4H + bid * 32;
            float gi = gate_s[b * 33 + jj]      + __ldg(&Prow[jj]);
            float gf = gate_s[b * 33 + 8 + jj]  + __ldg(&Prow[8 + jj]);
            float gg = gate_s[b * 33 + 16 + jj] + __ldg(&Prow[16 + jj]);
            float go = gate_s[b * 33 + 24 + jj] + __ldg(&Prow[24 + jj]);
            float c = c_s[p];
            float si = 1.f / (1.f + expf(-gi));
            float sf = 1.f / (1.f + expf(-gf));
            float so = 1.f / (1.f + expf(-go));
            float cn = sf * c + si * tanhf(gg);
            float hn = so * tanhf(cn);
            c_s[p] = cn;
            int jg = bid * 8 + jj;
            __half hv = __float2half_rn(hn);
            // fragment-ordered scatter write:
            //   frag = (b>>4)*64 + (jg>>4); lane = (b&7)*4 + ((jg&7)>>1)
            //   word = ((jg>>3)&1)*2 + ((b>>3)&1); byte = jg&1
            {
                int frag = ((b >> 4) << 6) + (jg >> 4);
                int lane = ((b & 7) << 2) + ((jg & 7) >> 1);
                int word = (((jg >> 3) & 1) << 1) | ((b >> 3) & 1);
                size_t off = (size_t)frag * 512 + lane * 16 + word * 4 + (jg & 1) * 2;
                *(__half*)(g_hfrag[(s + 1) & 1] + off) = hv;
            }
            if (!enc)
                Hdec16[(size_t)(t * 64 + b) * H_ + jg] = hv;
        }
        GSYNC();
    }
#undef GSYNC
}

// ---------------- launch ------------------------------------------------------------
extern "C" void kernel_launch(void* const* d_in, const int* in_sizes, int n_in,
                              void* d_out, int out_size)
{
    (void)in_sizes; (void)n_in; (void)out_size;
    const int*   seqs    = (const int*)  d_in[1];
    const float* enc_emb = (const float*)d_in[2];
    const float* enc_Wih = (const float*)d_in[3];
    const float* enc_Whh = (const float*)d_in[4];
    const float* enc_b   = (const float*)d_in[5];
    const float* dec_emb = (const float*)d_in[6];
    const float* dec_Wih = (const float*)d_in[7];
    const float* dec_Whh = (const float*)d_in[8];
    const float* dec_b   = (const float*)d_in[9];
    const float* out_W   = (const float*)d_in[10];
    const float* out_b   = (const float*)d_in[11];
    float* out = (float*)d_out;

    float *Penc, *Pdec, *biasr;
    __half *A16, *B16, *W16e, *W16d;
    cudaGetSymbolAddress((void**)&Penc, g_P_enc);
    cudaGetSymbolAddress((void**)&Pdec, g_P_dec);
    cudaGetSymbolAddress((void**)&A16,  g_A16);
    cudaGetSymbolAddress((void**)&B16,  g_B16);
    cudaGetSymbolAddress((void**)&W16e, g_W16_e);
    cudaGetSymbolAddress((void**)&W16d, g_W16_d);
    cudaGetSymbolAddress((void**)&biasr, g_bias_r);

    cudaFuncSetAttribute(mma_nt2<0>, cudaFuncAttributeMaxDynamicSharedMemorySize, GEMM_SMEM);
    cudaFuncSetAttribute(mma_nt2<1>, cudaFuncAttributeMaxDynamicSharedMemorySize, GEMM_SMEM);
    cudaFuncSetAttribute(lstm_rec_mma, cudaFuncAttributeMaxDynamicSharedMemorySize, REC_SMEM);

    // encoder vocab table: P_enc = enc_emb16 @ enc_Wih'(2-term)^T + b'  [8000,4096]
    to_f16<0><<<(MPAD_TAB * E_ + 255) / 256, 256>>>(enc_emb, A16, V_, MPAD_TAB, E_);
    split2_f16<1><<<(G4H * E_ + 255) / 256, 256>>>(enc_Wih, B16, G4H, G4H, E_);
    reorder_bias<<<16, 256>>>(enc_b, biasr);
    mma_nt2<0><<<dim3(G4H / 128, MPAD_TAB / 128), 256, GEMM_SMEM>>>(
        A16, B16, biasr, Penc, V_, G4H, E_, G4H);

    // decoder vocab table
    to_f16<0><<<(MPAD_TAB * E_ + 255) / 256, 256>>>(dec_emb, A16, V_, MPAD_TAB, E_);
    split2_f16<1><<<(G4H * E_ + 255) / 256, 256>>>(dec_Wih, B16, G4H, G4H, E_);
    reorder_bias<<<16, 256>>>(dec_b, biasr);
    mma_nt2<0><<<dim3(G4H / 128, MPAD_TAB / 128), 256, GEMM_SMEM>>>(
        A16, B16, biasr, Pdec, V_, G4H, E_, G4H);

    // recurrence weights (reordered, fp16 [hi|lo]); logits B operand; zero A16 pad tail
    split2_f16<1><<<(G4H * H_ + 255) / 256, 256>>>(enc_Whh, W16e, G4H, G4H, H_);
    split2_f16<1><<<(G4H * H_ + 255) / 256, 256>>>(dec_Whh, W16d, G4H, G4H, H_);
    split2_f16<0><<<(NPAD_LOGITS * H_ + 255) / 256, 256>>>(out_W, B16, V_, NPAD_LOGITS, H_);
    zero_buf<<<32, 256>>>((float4*)(A16 + (size_t)(TDEC * B_) * H_),
                          ((size_t)(MPAD_LOGITS - TDEC * B_) * H_ * 2) / 16);

    // serial recurrence (persistent grid; decoder h written directly into A16)
    lstm_rec_mma<<<NBLK, 256, REC_SMEM>>>(seqs, W16e, W16d, A16);

    // logits = Hdec16 @ outW16(2-term)^T + out_b -> [B, 255, V]
    mma_nt2<1><<<dim3(NPAD_LOGITS / 128, MPAD_LOGITS / 128), 256, GEMM_SMEM>>>(
        A16, B16, out_b, out, TDEC * B_, V_, H_, V_);
}

// round 17
// speedup vs baseline: 1.3950x; 1.2354x over previous
#include <cuda_runtime.h>
#include <cuda_fp16.h>
#include <math.h>
#include <stdint.h>

// Seq2seq LSTM forward, sm_103a.
//   (1) vocab tables P = embed16 @ Wih16'(2-term)^T + b'   (exact-ish P)
//   (2) persistent-grid recurrence: h fp16 fragment-ordered in global
//       (register-direct A), W fp16 HI-ONLY resident in smem, 1 MMA term
//   (3) logits = Hdec16 @ outW16(hi-only)^T + out_b
#define NBLK 128
#define B_   64
#define T_   256
#define V_   8000
#define E_   512
#define H_   1024
#define G4H  4096
#define TDEC 255
#define START_TOK 1

#define MPAD_LOGITS 16384
#define NPAD_LOGITS 8192
#define MPAD_TAB    8064

#define GEMM_SMEM_NT2 98304         // 2 stages x (A 16KB + Bhi 16KB + Blo 16KB)
#define GEMM_SMEM_NT1 65536         // 2 stages x (A 16KB + B 16KB)

// recurrence smem: W16hi 65536 | gate_s 8448 | c 2048 | tok 256
#define RW_OFF      0
#define RG_OFF      65536
#define RC_OFF      73984
#define RT_OFF      76032
#define REC_SMEM    76288

#define HFRAG_BYTES 131072          // one h buffer in fragment order (64x1024 fp16)

// ---------------- PTX helpers -------------------------------------------------------
__device__ __forceinline__ uint32_t smem_u32(const void* p) {
    uint32_t a;
    asm("{ .reg .u64 t; cvta.to.shared.u64 t, %1; cvt.u32.u64 %0, t; }" : "=r"(a) : "l"(p));
    return a;
}
__device__ __forceinline__ uint32_t sw128(uint32_t off) {
    return off ^ ((off >> 3) & 0x70);
}
__device__ __forceinline__ void cp_async16(uint32_t dst, const void* src) {
    asm volatile("cp.async.cg.shared.global [%0], [%1], 16;" :: "r"(dst), "l"(src) : "memory");
}
#define CP_COMMIT() asm volatile("cp.async.commit_group;" ::: "memory")
template<int N> __device__ __forceinline__ void cp_wait() {
    asm volatile("cp.async.wait_group %0;" :: "n"(N) : "memory");
}
__device__ __forceinline__ void ldsm_x4(uint32_t r[4], uint32_t addr) {
    asm volatile("ldmatrix.sync.aligned.m8n8.x4.shared.b16 {%0,%1,%2,%3}, [%4];"
                 : "=r"(r[0]), "=r"(r[1]), "=r"(r[2]), "=r"(r[3]) : "r"(addr));
}
__device__ __forceinline__ void ldg4(uint32_t r[4], const void* p) {
    asm volatile("ld.global.nc.v4.u32 {%0,%1,%2,%3}, [%4];"
                 : "=r"(r[0]), "=r"(r[1]), "=r"(r[2]), "=r"(r[3]) : "l"(p));
}
__device__ __forceinline__ void mma_f16(float d[4], const uint32_t a[4],
                                        uint32_t b0, uint32_t b1) {
    asm volatile(
        "mma.sync.aligned.m16n8k16.row.col.f32.f16.f16.f32 "
        "{%0,%1,%2,%3}, {%4,%5,%6,%7}, {%8,%9}, {%0,%1,%2,%3};"
        : "+f"(d[0]), "+f"(d[1]), "+f"(d[2]), "+f"(d[3])
        : "r"(a[0]), "r"(a[1]), "r"(a[2]), "r"(a[3]), "r"(b0), "r"(b1));
}

// ---------------- device scratch (allocation-free rule) -----------------------------
__device__ float g_P_enc[(size_t)V_ * G4H];
__device__ float g_P_dec[(size_t)V_ * G4H];
__device__ __half g_A16[(size_t)MPAD_LOGITS * H_];      // GEMM A operand (reused)
__device__ __half g_B16[(size_t)NPAD_LOGITS * 2 * H_];  // GEMM B operand (reused)
__device__ __half g_W16_e[(size_t)G4H * 1024];          // recurrence W hi, reordered
__device__ __half g_W16_d[(size_t)G4H * 1024];
// h double buffer in mma A-fragment order (see R16 layout comment)
__device__ __align__(256) unsigned char g_hfrag[2][HFRAG_BYTES];
__device__ float g_bias_r[G4H];
__device__ unsigned g_arrive = 0;
__device__ unsigned g_phase  = 0;

// ---------------- conversion helpers ------------------------------------------------
template<int REORD>
__global__ void to_f16(const float* __restrict__ X, __half* __restrict__ Y,
                       int M_in, int M_pad, int K)
{
    int idx = blockIdx.x * blockDim.x + threadIdx.x;
    if (idx >= M_pad * K) return;
    int m = idx / K, k = idx - m * K;
    int src = m;
    if (REORD) {
        int blk = m >> 5, r = m & 31;
        src = (r >> 3) * H_ + blk * 8 + (r & 7);
    }
    float x = (src < M_in) ? X[(size_t)src * K + k] : 0.f;
    Y[(size_t)m * K + k] = __float2half_rn(x);
}

template<int REORD>
__global__ void split2_f16(const float* __restrict__ X, __half* __restrict__ Y,
                           int M_in, int M_pad, int K)
{
    int idx = blockIdx.x * blockDim.x + threadIdx.x;
    if (idx >= M_pad * K) return;
    int m = idx / K, k = idx - m * K;
    int src = m;
    if (REORD) {
        int blk = m >> 5, r = m & 31;
        src = (r >> 3) * H_ + blk * 8 + (r & 7);
    }
    float x = (src < M_in) ? X[(size_t)src * K + k] : 0.f;
    __half hi = __float2half_rn(x);
    __half lo = __float2half_rn(x - __half2float(hi));
    size_t rb = (size_t)m * (2 * K);
    Y[rb + k]     = hi;
    Y[rb + K + k] = lo;
}

__global__ void reorder_bias(const float* __restrict__ b, float* __restrict__ br) {
    int m = blockIdx.x * blockDim.x + threadIdx.x;
    if (m >= G4H) return;
    int blk = m >> 5, r = m & 31;
    br[m] = b[(r >> 3) * H_ + blk * 8 + (r & 7)];
}

__global__ void zero_buf(float4* p, size_t n16) {
    size_t i = (size_t)blockIdx.x * blockDim.x + threadIdx.x;
    if (i < n16) p[i] = make_float4(0.f, 0.f, 0.f, 0.f);
}

// ---------------- fp16 HMMA GEMM, NT-term B -----------------------------------------
// C[M,N] = A16[M,K] @ (sum of NT B terms)[N,K]^T + bias; B stored [N, NT*K].
// 128x128 tiles, 64-col chunks (128B sw128 rows), 2-stage ring, 2 CTAs/SM.
// MODE 0: row-major C.  MODE 1: logits remap m=t*64+b -> C[(b*255+t)*ldC + n]
template<int MODE, int NT>
__global__ void __launch_bounds__(256, 2) mma_nt2(
    const __half* __restrict__ A16, const __half* __restrict__ B16,
    const float* __restrict__ bias, float* __restrict__ C,
    int M_eff, int N_eff, int K, int ldC)
{
    extern __shared__ __align__(1024) char dsm[];
    const uint32_t sb = smem_u32(dsm);
    const int tid = threadIdx.x;
    const int wid = tid >> 5, lid = tid & 31;
    const int wm = wid & 3, wn = wid >> 2;
    const int bm = blockIdx.y * 128, bn = blockIdx.x * 128;
    const int nch = K / 64;
    const int SSTG = (1 + NT) * 16384;

    auto loadT = [&](int ch) {
        uint32_t stg = sb + (ch & 1) * SSTG;
#pragma unroll
        for (int j = 0; j < 4; j++) {
            int i = tid + j * 256;
            int r = i >> 3, cb = (i & 7) * 16;
            uint32_t off = sw128((uint32_t)(r * 128 + cb));
            cp_async16(stg + off,
                       (const char*)A16 + ((size_t)(bm + r) * K + ch * 64) * 2 + cb);
            cp_async16(stg + 16384 + off,
                       (const char*)B16 + ((size_t)(bn + r) * NT * K + ch * 64) * 2 + cb);
            if (NT == 2)
                cp_async16(stg + 32768 + off,
                           (const char*)B16 + ((size_t)(bn + r) * NT * K + K + ch * 64) * 2 + cb);
        }
        CP_COMMIT();
    };

    float acc[2][8][4];
#pragma unroll
    for (int i = 0; i < 2; i++)
#pragma unroll
        for (int j = 0; j < 8; j++)
#pragma unroll
            for (int q = 0; q < 4; q++) acc[i][j][q] = 0.f;

    loadT(0);
    for (int i = 0; i < nch; i++) {
        if (i + 1 < nch) { loadT(i + 1); cp_wait<1>(); }
        else             { cp_wait<0>(); }
        __syncthreads();
        const uint32_t ab  = sb + (i & 1) * SSTG;
        const uint32_t bhb = ab + 16384;
        const uint32_t blb = ab + 32768;
#pragma unroll
        for (int ks = 0; ks < 4; ks++) {
            const uint32_t kb = (uint32_t)((ks * 16 + ((lid >> 4) << 3)) * 2);
            uint32_t a[2][4], b[4][4];
#pragma unroll
            for (int mi = 0; mi < 2; mi++)
                ldsm_x4(a[mi], ab + sw128((uint32_t)((wm * 32 + mi * 16 + (lid & 15)) * 128) + kb));
#pragma unroll
            for (int ni = 0; ni < 4; ni++)
                ldsm_x4(b[ni], bhb + sw128((uint32_t)((wn * 64 + ni * 16 + (lid & 15)) * 128) + kb));
#pragma unroll
            for (int mi = 0; mi < 2; mi++)
#pragma unroll
                for (int ni = 0; ni < 4; ni++) {
                    mma_f16(acc[mi][2 * ni + 0], a[mi], b[ni][0], b[ni][2]);
                    mma_f16(acc[mi][2 * ni + 1], a[mi], b[ni][1], b[ni][3]);
                }
            if (NT == 2) {
#pragma unroll
                for (int ni = 0; ni < 4; ni++)
                    ldsm_x4(b[ni], blb + sw128((uint32_t)((wn * 64 + ni * 16 + (lid & 15)) * 128) + kb));
#pragma unroll
                for (int mi = 0; mi < 2; mi++)
#pragma unroll
                    for (int ni = 0; ni < 4; ni++) {
                        mma_f16(acc[mi][2 * ni + 0], a[mi], b[ni][0], b[ni][2]);
                        mma_f16(acc[mi][2 * ni + 1], a[mi], b[ni][1], b[ni][3]);
                    }
            }
        }
        __syncthreads();
    }

#pragma unroll
    for (int mi = 0; mi < 2; mi++) {
        int m0 = bm + wm * 32 + mi * 16 + (lid >> 2);
#pragma unroll
        for (int half = 0; half < 2; half++) {
            int m = m0 + half * 8;
            if (m >= M_eff) continue;
            size_t obase;
            if (MODE == 0) obase = (size_t)m * ldC;
            else {
                int t = m >> 6, b = m & 63;
                obase = ((size_t)b * TDEC + t) * ldC;
            }
#pragma unroll
            for (int nj = 0; nj < 8; nj++) {
                int n = bn + wn * 64 + nj * 8 + (lid & 3) * 2;
                float v0 = acc[mi][nj][half * 2 + 0];
                float v1 = acc[mi][nj][half * 2 + 1];
                if (n < N_eff)     C[obase + n]     = v0 + __ldg(&bias[n]);
                if (n + 1 < N_eff) C[obase + n + 1] = v1 + __ldg(&bias[n + 1]);
            }
        }
    }
}

// ---------------- persistent HMMA LSTM recurrence (register-direct A, 1-term W) -----
// 128 blocks x 256 thr; block owns 32 reordered gate rows (4 gates x 8 hidden units).
// W16hi (32 x 1024 fp16, sw128) resident in smem. h read straight from
// fragment-ordered global: 16 kk x 4 ks, one LDG.128 per fragment per lane,
// depth-2 prefetch ring. Per ks: 1 ldsm + 2 MMA (fp32 accum).
__global__ void __launch_bounds__(256, 1) lstm_rec_mma(
    const int* __restrict__ seqs,
    const __half* __restrict__ W16_e,
    const __half* __restrict__ W16_d,
    __half* __restrict__ Hdec16)
{
    extern __shared__ __align__(1024) char dsm[];
    const uint32_t sb = smem_u32(dsm);
    float* gate_s = (float*)(dsm + RG_OFF);      // [64][33]
    float* c_s    = (float*)(dsm + RC_OFF);      // [512]: p = jj*64 + b
    int*   tok_s  = (int*)  (dsm + RT_OFF);

    const int tid = threadIdx.x;
    const int bid = blockIdx.x;
    const int wid = tid >> 5, lid = tid & 31;
    const int wm = wid & 3, wn = wid >> 2;

    unsigned base = 0;
    if (tid == 0) base = atomicAdd(&g_phase, 0u);   // replay-safe phase baseline
    unsigned tgt = 0;

    for (int i = bid * 256 + tid; i < HFRAG_BYTES / 4; i += NBLK * 256)
        ((uint32_t*)g_hfrag[0])[i] = 0u;
    c_s[tid] = 0.f; c_s[tid + 256] = 0.f;

    // W loader: 32 rows x 2048 bytes (hi only); smem chunk kk = 32 rows x 128 B
    auto loadW = [&](const __half* Wsrc) {
#pragma unroll
        for (int j = 0; j < 16; j++) {
            int i = tid + j * 256;           // 0..4095
            int row = i >> 7;                // 0..31
            int cb  = (i & 127) * 16;        // 0..2032
            int ci  = cb >> 7, inner = cb & 127;
            cp_async16(sb + RW_OFF + ci * 4096 + sw128((uint32_t)(row * 128 + inner)),
                       (const char*)Wsrc + (size_t)(bid * 32 + row) * 2048 + cb);
        }
        CP_COMMIT();
    };
    loadW(W16_e);

#define GSYNC() do {                                                     \
    __syncthreads();                                                     \
    if (tid == 0) {                                                      \
        ++tgt;                                                           \
        __threadfence();                                                 \
        unsigned prev_ = atomicAdd(&g_arrive, 1u);                       \
        if (prev_ == NBLK - 1) {                                         \
            atomicExch(&g_arrive, 0u);                                   \
            __threadfence();                                             \
            atomicAdd(&g_phase, 1u);                                     \
        } else {                                                         \
            volatile unsigned* vp_ = &g_phase;                           \
            while ((unsigned)(*vp_ - base) < tgt)                        \
                __nanosleep(32);                                         \
            __threadfence();                                             \
        }                                                                \
    }                                                                    \
    __syncthreads();                                                     \
} while (0)

    GSYNC();              // h0 visible grid-wide
    cp_wait<0>();         // encoder W resident
    __syncthreads();

    for (int s = 0; s < T_ + TDEC; s++) {
        const bool enc = (s < T_);
        const int t = enc ? s : s - T_;
        const float* __restrict__ P = enc ? g_P_enc : g_P_dec;
        const char* abase = (const char*)g_hfrag[s & 1]
                          + (size_t)wm * 32768 + (size_t)lid * 16;

        if (s == T_) {                      // decoder weight swap (one-time stall)
            loadW(W16_d);
            cp_wait<0>();
            __syncthreads();
        }
        if (tid < B_)
            tok_s[tid] = enc ? seqs[tid * T_ + t]
                             : (t == 0 ? START_TOK : seqs[tid * T_ + t]);

        float accL[4] = {0.f, 0.f, 0.f, 0.f};
        float accH[4] = {0.f, 0.f, 0.f, 0.f};

        uint32_t Abuf[3][4][4];
#pragma unroll
        for (int kk = 0; kk < 2; kk++)
#pragma unroll
            for (int ks = 0; ks < 4; ks++)
                ldg4(Abuf[kk][ks], abase + (kk * 4 + ks) * 512);

#pragma unroll
        for (int kk = 0; kk < 16; kk++) {
            if (kk + 2 < 16) {
#pragma unroll
                for (int ks = 0; ks < 4; ks++)
                    ldg4(Abuf[(kk + 2) % 3][ks], abase + ((kk + 2) * 4 + ks) * 512);
            }
            const uint32_t wbh = sb + RW_OFF + kk * 4096;
#pragma unroll
            for (int ks = 0; ks < 4; ks++) {
                const uint32_t kb = (uint32_t)((ks * 16 + ((lid >> 4) << 3)) * 2);
                const uint32_t brow = sw128((uint32_t)((wn * 16 + (lid & 15)) * 128) + kb);
                uint32_t bh[4];
                ldsm_x4(bh, wbh + brow);
                mma_f16(accL, Abuf[kk % 3][ks], bh[0], bh[2]);
                mma_f16(accH, Abuf[kk % 3][ks], bh[1], bh[3]);
            }
        }

        {
            int r0 = wm * 16 + (lid >> 2);
            int c0 = wn * 16 + (lid & 3) * 2;
            gate_s[r0 * 33 + c0]           = accL[0];
            gate_s[r0 * 33 + c0 + 1]       = accL[1];
            gate_s[(r0 + 8) * 33 + c0]     = accL[2];
            gate_s[(r0 + 8) * 33 + c0 + 1] = accL[3];
            gate_s[r0 * 33 + c0 + 8]       = accH[0];
            gate_s[r0 * 33 + c0 + 9]       = accH[1];
            gate_s[(r0 + 8) * 33 + c0 + 8] = accH[2];
            gate_s[(r0 + 8) * 33 + c0 + 9] = accH[3];
        }
        __syncthreads();

#pragma unroll
        for (int u = 0; u < 2; u++) {
            int p = tid + u * 256;
            int b = p & 63, jj = p >> 6;
            const float* Prow = P + (size_t)tok_s[b] * G4H + bid * 32;
            float gi = gate_s[b * 33 + jj]      + __ldg(&Prow[jj]);
            float gf = gate_s[b * 33 + 8 + jj]  + __ldg(&Prow[8 + jj]);
            float gg = gate_s[b * 33 + 16 + jj] + __ldg(&Prow[16 + jj]);
            float go = gate_s[b * 33 + 24 + jj] + __ldg(&Prow[24 + jj]);
            float c = c_s[p];
            float si = 1.f / (1.f + expf(-gi));
            float sf = 1.f / (1.f + expf(-gf));
            float so = 1.f / (1.f + expf(-go));
            float cn = sf * c + si * tanhf(gg);
            float hn = so * tanhf(cn);
            c_s[p] = cn;
            int jg = bid * 8 + jj;
            __half hv = __float2half_rn(hn);
            {   // fragment-ordered scatter write (same mapping as R16)
                int frag = ((b >> 4) << 6) + (jg >> 4);
                int lane = ((b & 7) << 2) + ((jg & 7) >> 1);
                int word = (((jg >> 3) & 1) << 1) | ((b >> 3) & 1);
                size_t off = (size_t)frag * 512 + lane * 16 + word * 4 + (jg & 1) * 2;
                *(__half*)(g_hfrag[(s + 1) & 1] + off) = hv;
            }
            if (!enc)
                Hdec16[(size_t)(t * 64 + b) * H_ + jg] = hv;
        }
        GSYNC();
    }
#undef GSYNC
}

// ---------------- launch ------------------------------------------------------------
extern "C" void kernel_launch(void* const* d_in, const int* in_sizes, int n_in,
                              void* d_out, int out_size)
{
    (void)in_sizes; (void)n_in; (void)out_size;
    const int*   seqs    = (const int*)  d_in[1];
    const float* enc_emb = (const float*)d_in[2];
    const float* enc_Wih = (const float*)d_in[3];
    const float* enc_Whh = (const float*)d_in[4];
    const float* enc_b   = (const float*)d_in[5];
    const float* dec_emb = (const float*)d_in[6];
    const float* dec_Wih = (const float*)d_in[7];
    const float* dec_Whh = (const float*)d_in[8];
    const float* dec_b   = (const float*)d_in[9];
    const float* out_W   = (const float*)d_in[10];
    const float* out_b   = (const float*)d_in[11];
    float* out = (float*)d_out;

    float *Penc, *Pdec, *biasr;
    __half *A16, *B16, *W16e, *W16d;
    cudaGetSymbolAddress((void**)&Penc, g_P_enc);
    cudaGetSymbolAddress((void**)&Pdec, g_P_dec);
    cudaGetSymbolAddress((void**)&A16,  g_A16);
    cudaGetSymbolAddress((void**)&B16,  g_B16);
    cudaGetSymbolAddress((void**)&W16e, g_W16_e);
    cudaGetSymbolAddress((void**)&W16d, g_W16_d);
    cudaGetSymbolAddress((void**)&biasr, g_bias_r);

    cudaFuncSetAttribute(mma_nt2<0, 2>, cudaFuncAttributeMaxDynamicSharedMemorySize, GEMM_SMEM_NT2);
    cudaFuncSetAttribute(mma_nt2<1, 1>, cudaFuncAttributeMaxDynamicSharedMemorySize, GEMM_SMEM_NT1);
    cudaFuncSetAttribute(lstm_rec_mma, cudaFuncAttributeMaxDynamicSharedMemorySize, REC_SMEM);

    // encoder vocab table: P_enc = enc_emb16 @ enc_Wih'(2-term)^T + b'  [8000,4096]
    to_f16<0><<<(MPAD_TAB * E_ + 255) / 256, 256>>>(enc_emb, A16, V_, MPAD_TAB, E_);
    split2_f16<1><<<(G4H * E_ + 255) / 256, 256>>>(enc_Wih, B16, G4H, G4H, E_);
    reorder_bias<<<16, 256>>>(enc_b, biasr);
    mma_nt2<0, 2><<<dim3(G4H / 128, MPAD_TAB / 128), 256, GEMM_SMEM_NT2>>>(
        A16, B16, biasr, Penc, V_, G4H, E_, G4H);

    // decoder vocab table
    to_f16<0><<<(MPAD_TAB * E_ + 255) / 256, 256>>>(dec_emb, A16, V_, MPAD_TAB, E_);
    split2_f16<1><<<(G4H * E_ + 255) / 256, 256>>>(dec_Wih, B16, G4H, G4H, E_);
    reorder_bias<<<16, 256>>>(dec_b, biasr);
    mma_nt2<0, 2><<<dim3(G4H / 128, MPAD_TAB / 128), 256, GEMM_SMEM_NT2>>>(
        A16, B16, biasr, Pdec, V_, G4H, E_, G4H);

    // recurrence weights (reordered, hi only); logits B operand (hi only); A16 pad tail
    to_f16<1><<<(G4H * H_ + 255) / 256, 256>>>(enc_Whh, W16e, G4H, G4H, H_);
    to_f16<1><<<(G4H * H_ + 255) / 256, 256>>>(dec_Whh, W16d, G4H, G4H, H_);
    to_f16<0><<<(NPAD_LOGITS * H_ + 255) / 256, 256>>>(out_W, B16, V_, NPAD_LOGITS, H_);
    zero_buf<<<32, 256>>>((float4*)(A16 + (size_t)(TDEC * B_) * H_),
                          ((size_t)(MPAD_LOGITS - TDEC * B_) * H_ * 2) / 16);

    // serial recurrence (persistent grid; decoder h written directly into A16)
    lstm_rec_mma<<<NBLK, 256, REC_SMEM>>>(seqs, W16e, W16d, A16);

    // logits = Hdec16 @ outW16(hi)^T + out_b -> [B, 255, V]
    mma_nt2<1, 1><<<dim3(NPAD_LOGITS / 128, MPAD_LOGITS / 128), 256, GEMM_SMEM_NT1>>>(
        A16, B16, out_b, out, TDEC * B_, V_, H_, V_);
}